// round 9
// baseline (speedup 1.0000x reference)
#include <cuda_runtime.h>
#include <cmath>

#define TOKS 4096          // B_SZ * L
#define DD   1024          // D
#define NN   16            // N
#define ROWF ((2*DD + 1) * NN)   // 32784 floats per token in output

// scratch (no cudaMalloc allowed)
__device__ float g_B[TOKS][NN];
__device__ float g_C[TOKS][NN];
__device__ float g_s[TOKS];
__device__ float g_R[DD * NN];        // 1 / A

__device__ __forceinline__ float softplus_f(float z) {
    // matches jax.nn.softplus: max(z,0) + log1p(exp(-|z|))
    return fmaxf(z, 0.f) + log1pf(__expf(-fabsf(z)));
}

// ---------------------------------------------------------------------------
// Phase 1 (v3): projections. Warp per token-pair (t, t+2048) -> weight LDS
// amortized over 2 tokens. Weights staged in TWO 66 KB k-halves so smem =
// 67.6 KB -> 2 CTAs/SM (fill of one CTA overlaps compute of the other).
// 256 blocks x 256 threads = 2048 warp-pairs, full SM coverage.
// Block 0 also builds the 1/A table.
// ---------------------------------------------------------------------------
__global__ __launch_bounds__(256, 2) void proj_kernel(
    const float* __restrict__ x, const float* __restrict__ Wb,
    const float* __restrict__ Wc, const float* __restrict__ Wd,
    const float* __restrict__ A)
{
    extern __shared__ float4 sw[];   // 33 rows * 128 float4 = 67584 B

    if (blockIdx.x == 0) {           // one-time 1/A table
        for (int i = threadIdx.x; i < DD * NN; i += blockDim.x)
            g_R[i] = __frcp_rn(A[i]);
    }

    const int wid  = threadIdx.x >> 5;               // 0..7
    const int lane = threadIdx.x & 31;
    const int pr   = blockIdx.x * 8 + wid;           // pair index 0..2047
    const int t0 = pr, t1 = pr + TOKS / 2;
    const float4* x0 = (const float4*)(x + (size_t)t0 * DD);
    const float4* x1 = (const float4*)(x + (size_t)t1 * DD);
    const float4* wb4 = (const float4*)Wb;
    const float4* wc4 = (const float4*)Wc;
    const float4* wd4 = (const float4*)Wd;

    float acc0[33], acc1[33];
#pragma unroll
    for (int j = 0; j < 33; j++) { acc0[j] = 0.f; acc1[j] = 0.f; }

#pragma unroll
    for (int h = 0; h < 2; h++) {
        // fill this k-half of the weights: rows x 128 float4
        if (h) __syncthreads();      // protect smem reuse between halves
        for (int i = threadIdx.x; i < 33 * 128; i += blockDim.x) {
            int row = i >> 7, col = (i & 127) + h * 128;
            float4 v;
            if (row < 16)      v = __ldg(wb4 + row * 256 + col);
            else if (row < 32) v = __ldg(wc4 + (row - 16) * 256 + col);
            else               v = __ldg(wd4 + col);
            sw[i] = v;
        }
        __syncthreads();

#pragma unroll
        for (int i = 0; i < 4; i++) {
            int cl = i * 32 + lane;                  // 0..127 within half
            float4 a = __ldg(x0 + h * 128 + cl);
            float4 b = __ldg(x1 + h * 128 + cl);
#pragma unroll
            for (int j = 0; j < 33; j++) {
                float4 w = sw[j * 128 + cl];
                acc0[j] = fmaf(a.x, w.x, fmaf(a.y, w.y, fmaf(a.z, w.z, fmaf(a.w, w.w, acc0[j]))));
                acc1[j] = fmaf(b.x, w.x, fmaf(b.y, w.y, fmaf(b.z, w.z, fmaf(b.w, w.w, acc1[j]))));
            }
        }
    }

#pragma unroll
    for (int j = 0; j < 33; j++) {
#pragma unroll
        for (int o = 16; o > 0; o >>= 1) {
            acc0[j] += __shfl_xor_sync(0xffffffffu, acc0[j], o);
            acc1[j] += __shfl_xor_sync(0xffffffffu, acc1[j], o);
        }
    }

    if (lane == 0) {
#pragma unroll
        for (int j = 0; j < 16; j++) { g_B[t0][j] = acc0[j];      g_B[t1][j] = acc1[j]; }
#pragma unroll
        for (int j = 0; j < 16; j++) { g_C[t0][j] = acc0[16 + j]; g_C[t1][j] = acc1[16 + j]; }
        g_s[t0] = acc0[32];
        g_s[t1] = acc1[32];
    }
}

// ---------------------------------------------------------------------------
// Phase 2 (FROZEN — proven ~93-96 us): expansion + 537 MB streaming stores.
// Per-token smem stage computes Delta = softplus once per d and stages the x
// row; lean hot loop; 3 CTAs/SM.
//   A_bar    = exp(Delta * A[d,n])
//   deltaB_x = (A_bar - 1) * R[d,n] * B[tok,n] * x[tok,d]   (Delta cancels)
// ---------------------------------------------------------------------------
__global__ __launch_bounds__(512, 3) void ssm_kernel(
    const float* __restrict__ x, const float* __restrict__ A,
    const float* __restrict__ dparam, float* __restrict__ out)
{
    __shared__ float sD[DD];   // Delta per d
    __shared__ float sX[DD];   // x row

    const int tid = threadIdx.x;
    const int q   = tid & 3;    // n-quad 0..3
    const int dof = tid >> 2;   // 0..127
    const float4* A4 = (const float4*)A;
    const float4* R4 = (const float4*)g_R;

    for (int tok = blockIdx.x; tok < TOKS; tok += gridDim.x) {
        const float s = g_s[tok];
        float4 Bq = *((const float4*)g_B[tok] + q);
        const float* xr = x + (size_t)tok * DD;
        float* ob = out + (size_t)tok * ROWF;

        // stage Delta (1 softplus per d) and the x row
#pragma unroll
        for (int h = 0; h < 2; h++) {
            int d = tid + h * 512;
            sD[d] = softplus_f(s + __ldg(dparam + d));
            sX[d] = __ldg(xr + d);
        }
        __syncthreads();

        if (tid < 4)
            __stcs((float4*)(ob + 2 * DD * NN) + tid,
                   *((const float4*)g_C[tok] + tid));

#pragma unroll
        for (int it = 0; it < 8; it++) {
            int d = dof + it * 128;
            float Delta = sD[d];
            float xd    = sX[d];
            float4 a = __ldg(A4 + d * 4 + q);
            float4 r = __ldg(R4 + d * 4 + q);
            float4 eo, bo;
#define COMP(f)                                                              \
            {                                                                \
                float dA = Delta * a.f;                                      \
                float e  = __expf(dA);                                       \
                float em1 = (fabsf(dA) < 0.015625f)                          \
                    ? dA * fmaf(dA, fmaf(dA, 0.16666667f, 0.5f), 1.f)        \
                    : (e - 1.f);                                             \
                eo.f = e;                                                    \
                bo.f = em1 * (r.f * (Bq.f * xd));                            \
            }
            COMP(x) COMP(y) COMP(z) COMP(w)
#undef COMP
            __stcs((float4*)ob + (size_t)d * 4 + q, eo);
            __stcs((float4*)ob + (size_t)DD * 4 + (size_t)d * 4 + q, bo);
        }
        __syncthreads();   // sD/sX reused next token
    }
}

// ---------------------------------------------------------------------------
extern "C" void kernel_launch(void* const* d_in, const int* in_sizes, int n_in,
                              void* d_out, int out_size)
{
    const float* x  = (const float*)d_in[0];
    const float* Wb = (const float*)d_in[1];
    const float* Wc = (const float*)d_in[2];
    const float* Wd = (const float*)d_in[3];
    const float* A  = (const float*)d_in[4];
    const float* dp = (const float*)d_in[5];
    float* out = (float*)d_out;

    const int SMEM1 = 33 * 128 * 16;                   // 67584 B
    cudaFuncSetAttribute(proj_kernel, cudaFuncAttributeMaxDynamicSharedMemorySize, SMEM1);

    // Phase 1: k-halved smem weights, 2 CTAs/SM, full SM coverage
    proj_kernel<<<256, 256, SMEM1>>>(x, Wb, Wc, Wd, A);
    // Phase 2: frozen hot kernel
    ssm_kernel<<<456, 512>>>(x, A, dp, out);
}

// round 10
// speedup vs baseline: 1.1586x; 1.1586x over previous
#include <cuda_runtime.h>
#include <cmath>

#define TOKS 4096          // B_SZ * L
#define DD   1024          // D
#define NN   16            // N
#define ROWF ((2*DD + 1) * NN)   // 32784 floats per token in output
#define STRIP 8            // tokens per block

// 1/A table (no cudaMalloc allowed)
__device__ float g_R[DD * NN];

__global__ void init_R_kernel(const float* __restrict__ A)
{
    int i = blockIdx.x * blockDim.x + threadIdx.x;
    if (i < DD * NN) g_R[i] = __frcp_rn(A[i]);
}

__device__ __forceinline__ float softplus_f(float z) {
    // matches jax.nn.softplus: max(z,0) + log1p(exp(-|z|))
    return fmaxf(z, 0.f) + log1pf(__expf(-fabsf(z)));
}

__device__ __forceinline__ float dot4(float4 a, float4 b, float acc) {
    return fmaf(a.x, b.x, fmaf(a.y, b.y, fmaf(a.z, b.z, fmaf(a.w, b.w, acc))));
}

// ---------------------------------------------------------------------------
// Strip-fused kernel: block = 8 consecutive tokens.
// Phase A (bulk proj): warp = 4 W-rows x 4 tokens register tile; W float4s
//   held in registers across tokens; all 264 dots of the strip computed in
//   parallel, ONE barrier. Results -> sP[33][8] (1 KB smem).
// Phase B (proven R7 hot loop): per token, stage Delta/x in smem, then the
//   lean expansion + 537 MB streaming stores.
//   A_bar    = exp(Delta * A[d,n])
//   deltaB_x = (A_bar - 1) * R[d,n] * B[tok,n] * x[tok,d]   (Delta cancels)
// ---------------------------------------------------------------------------
__global__ __launch_bounds__(512, 2) void fused_kernel(
    const float* __restrict__ x,  const float* __restrict__ Wb,
    const float* __restrict__ Wc, const float* __restrict__ Wd,
    const float* __restrict__ A,  const float* __restrict__ dparam,
    float* __restrict__ out)
{
    __shared__ float sP[33][STRIP];   // rows 0-15: B, 16-31: C, 32: s
    __shared__ float sD[DD];          // Delta per d (one token at a time)
    __shared__ float sX[DD];          // x row

    const int tid  = threadIdx.x;
    const int wid  = tid >> 5;
    const int lane = tid & 31;
    const int base = blockIdx.x * STRIP;

    // ---------------- phase A: bulk projections ----------------
    {
        const int g  = wid >> 1;            // row-group 0..7
        const int th = (wid & 1) * 4;       // token-half offset 0 or 4
        const int rbase = (g < 4) ? 4 * g : 4 * (g - 4);
        const float* Wsel = (g < 4) ? Wb : Wc;
        const float4* w4  = (const float4*)(Wsel + (size_t)rbase * DD); // 4 consecutive rows
        const float4* xb4 = (const float4*)(x + (size_t)(base + th) * DD); // 4 consecutive tokens
        const float4* wd4 = (const float4*)Wd;

        float acc[4][4];                    // [row][token]
        float accd[4];                      // Wd row (warps 0,1 only)
#pragma unroll
        for (int j = 0; j < 4; j++)
#pragma unroll
            for (int t = 0; t < 4; t++) acc[j][t] = 0.f;
#pragma unroll
        for (int t = 0; t < 4; t++) accd[t] = 0.f;

#pragma unroll
        for (int i = 0; i < 8; i++) {
            const int c = i * 32 + lane;    // float4 index 0..255
            float4 w0 = __ldg(w4 + 0 * 256 + c);
            float4 w1 = __ldg(w4 + 1 * 256 + c);
            float4 w2 = __ldg(w4 + 2 * 256 + c);
            float4 w3 = __ldg(w4 + 3 * 256 + c);
            float4 dv;
            if (wid < 2) dv = __ldg(wd4 + c);
#pragma unroll
            for (int t = 0; t < 4; t++) {
                float4 xv = __ldg(xb4 + t * 256 + c);
                acc[0][t] = dot4(w0, xv, acc[0][t]);
                acc[1][t] = dot4(w1, xv, acc[1][t]);
                acc[2][t] = dot4(w2, xv, acc[2][t]);
                acc[3][t] = dot4(w3, xv, acc[3][t]);
                if (wid < 2) accd[t] = dot4(dv, xv, accd[t]);
            }
        }

#pragma unroll
        for (int j = 0; j < 4; j++)
#pragma unroll
            for (int t = 0; t < 4; t++)
#pragma unroll
                for (int o = 16; o > 0; o >>= 1)
                    acc[j][t] += __shfl_xor_sync(0xffffffffu, acc[j][t], o);
        if (wid < 2)
#pragma unroll
            for (int t = 0; t < 4; t++)
#pragma unroll
                for (int o = 16; o > 0; o >>= 1)
                    accd[t] += __shfl_xor_sync(0xffffffffu, accd[t], o);

        if (lane == 0) {
            const int rowout = (g < 4) ? rbase : 16 + rbase;
#pragma unroll
            for (int j = 0; j < 4; j++)
#pragma unroll
                for (int t = 0; t < 4; t++)
                    sP[rowout + j][th + t] = acc[j][t];
            if (wid < 2)
#pragma unroll
                for (int t = 0; t < 4; t++) sP[32][th + t] = accd[t];
        }
    }
    __syncthreads();

    // ---------------- phase B: expansion (proven hot loop) ----------------
    const int q   = tid & 3;    // n-quad 0..3
    const int dof = tid >> 2;   // 0..127
    const float4* A4 = (const float4*)A;
    const float4* R4 = (const float4*)g_R;

#pragma unroll 1
    for (int t = 0; t < STRIP; t++) {
        const int tok = base + t;
        const float s = sP[32][t];
        const float* xr = x + (size_t)tok * DD;
        float* ob = out + (size_t)tok * ROWF;

        // stage Delta (1 softplus per d) and the x row (L1-hot from phase A)
#pragma unroll
        for (int h = 0; h < 2; h++) {
            int d = tid + h * 512;
            sD[d] = softplus_f(s + __ldg(dparam + d));
            sX[d] = __ldg(xr + d);
        }
        __syncthreads();

        float4 Bq = make_float4(sP[4 * q + 0][t], sP[4 * q + 1][t],
                                sP[4 * q + 2][t], sP[4 * q + 3][t]);

        if (tid < 16)
            __stcs(ob + 2 * DD * NN + tid, sP[16 + tid][t]);

#pragma unroll
        for (int it = 0; it < 8; it++) {
            int d = dof + it * 128;
            float Delta = sD[d];
            float xd    = sX[d];
            float4 a = __ldg(A4 + d * 4 + q);
            float4 r = __ldg(R4 + d * 4 + q);
            float4 eo, bo;
#define COMP(f)                                                              \
            {                                                                \
                float dA = Delta * a.f;                                      \
                float e  = __expf(dA);                                       \
                float em1 = (fabsf(dA) < 0.015625f)                          \
                    ? dA * fmaf(dA, fmaf(dA, 0.16666667f, 0.5f), 1.f)        \
                    : (e - 1.f);                                             \
                eo.f = e;                                                    \
                bo.f = em1 * (r.f * (Bq.f * xd));                            \
            }
            COMP(x) COMP(y) COMP(z) COMP(w)
#undef COMP
            __stcs((float4*)ob + (size_t)d * 4 + q, eo);
            __stcs((float4*)ob + (size_t)DD * 4 + (size_t)d * 4 + q, bo);
        }
        __syncthreads();   // sD/sX reused next token
    }
}

// ---------------------------------------------------------------------------
extern "C" void kernel_launch(void* const* d_in, const int* in_sizes, int n_in,
                              void* d_out, int out_size)
{
    const float* x  = (const float*)d_in[0];
    const float* Wb = (const float*)d_in[1];
    const float* Wc = (const float*)d_in[2];
    const float* Wd = (const float*)d_in[3];
    const float* A  = (const float*)d_in[4];
    const float* dp = (const float*)d_in[5];
    float* out = (float*)d_out;

    init_R_kernel<<<32, 512>>>(A);                        // 16K rcp, ~2 us
    fused_kernel<<<TOKS / STRIP, 512>>>(x, Wb, Wc, Wd, A, dp, out);  // 512 blocks
}